// round 12
// baseline (speedup 1.0000x reference)
#include <cuda_runtime.h>
#include <cuda_fp16.h>

#define N_USER    50000
#define N_ITEM    10000
#define NUM_NODES 60000
#define EMB_D     64
#define N_EDGES   2000000
#define N_GROUPS12 (N_EDGES / 12)   // 12 edges per 8-lane group (+ tail kernel)
#define N_TAIL     (N_EDGES - N_GROUPS12 * 12)

// Table scale: keeps fp16 products in normal range.
#define TBL_SCALE      512.0f
#define INV_TBL_SCALE2 (1.0f / (512.0f * 512.0f))   // 2^-18

// Fused, pre-scaled node table in fp16: row = 64 half = 128 B (one L1 line).
__device__ __half g_nodes[NUM_NODES * EMB_D];

// Phase 1: build fused node table (fp32 math, fp16 store, x512 pre-scale).
__global__ void build_nodes_kernel(const float* __restrict__ user_emb,
                                   const float* __restrict__ item_emb,
                                   const float* __restrict__ tag_emb,
                                   const float* __restrict__ testid_emb,
                                   const float* __restrict__ bigcat_emb,
                                   const float* __restrict__ daydiff_emb,
                                   const int*  __restrict__ item_tags,
                                   const int*  __restrict__ item_testids,
                                   const int*  __restrict__ item_bigcat,
                                   const int*  __restrict__ user_daydiff) {
    unsigned int t = blockIdx.x * blockDim.x + threadIdx.x;
    unsigned int node = t >> 4;
    unsigned int sub  = t & 15u;
    if (node >= NUM_NODES) return;
    unsigned int off = sub * 4u;

    const float alpha = 1.0f / 3.0f;
    float4 r;
    if (node < N_USER) {
        const float s = 0.5f * alpha * TBL_SCALE;
        int dd = user_daydiff[node];
        float4 u = *(const float4*)(user_emb    + (size_t)node * EMB_D + off);
        float4 d = *(const float4*)(daydiff_emb + (size_t)dd   * EMB_D + off);
        r.x = (u.x + d.x) * s;
        r.y = (u.y + d.y) * s;
        r.z = (u.z + d.z) * s;
        r.w = (u.w + d.w) * s;
    } else {
        const float s = 0.25f * alpha * TBL_SCALE;
        unsigned int it = node - N_USER;
        int tg = item_tags[it];
        int ts = item_testids[it];
        int bc = item_bigcat[it];
        float4 a = *(const float4*)(item_emb   + (size_t)it * EMB_D + off);
        float4 b = *(const float4*)(tag_emb    + (size_t)tg * EMB_D + off);
        float4 c = *(const float4*)(testid_emb + (size_t)ts * EMB_D + off);
        float4 e = *(const float4*)(bigcat_emb + (size_t)bc * EMB_D + off);
        r.x = (a.x + b.x + c.x + e.x) * s;
        r.y = (a.y + b.y + c.y + e.y) * s;
        r.z = (a.z + b.z + c.z + e.z) * s;
        r.w = (a.w + b.w + c.w + e.w) * s;
    }
    __half2 h0 = __floats2half2_rn(r.x, r.y);
    __half2 h1 = __floats2half2_rn(r.z, r.w);
    uint2 packed;
    packed.x = *(const unsigned int*)&h0;
    packed.y = *(const unsigned int*)&h1;
    *(uint2*)((char*)g_nodes + (size_t)node * 128u + sub * 8u) = packed;
}

// half2 partial dot of 16 halves (one uint4 pair): 4 HMUL2 + 3 HADD2.
__device__ __forceinline__ __half2 pdot(uint4 a, uint4 b) {
    const __half2* pa = (const __half2*)&a;
    const __half2* pb = (const __half2*)&b;
    __half2 m0 = __hmul2(pa[0], pb[0]);
    __half2 m1 = __hmul2(pa[1], pb[1]);
    __half2 m2 = __hmul2(pa[2], pb[2]);
    __half2 m3 = __hmul2(pa[3], pb[3]);
    return __hadd2(__hadd2(m0, m1), __hadd2(m2, m3));
}

__device__ __forceinline__ __half2 shfl_h2(__half2 v, int ofs) {
    unsigned int u = *(unsigned int*)&v;
    u = __shfl_xor_sync(0xffffffffu, u, ofs);
    return *(__half2*)&u;
}

// Phase 2: 12 edges per 8-lane group, ALL 24 LDG.128 gathers front-batched
// flat (no consumes interposed), regs capped at 51 via launch_bounds(256,5).
__global__ __launch_bounds__(256, 5) void edge_dot_kernel(
        const int4* __restrict__ src4,
        const int4* __restrict__ dst4,
        float* __restrict__ out) {
    unsigned int t = blockIdx.x * blockDim.x + threadIdx.x;
    unsigned int g   = t >> 3;
    unsigned int sub = t & 7u;
    if (g >= N_GROUPS12) return;

    int4 s0 = src4[g * 3u + 0u];
    int4 s1 = src4[g * 3u + 1u];
    int4 s2 = src4[g * 3u + 2u];
    int4 d0 = dst4[g * 3u + 0u];
    int4 d1 = dst4[g * 3u + 1u];
    int4 d2 = dst4[g * 3u + 2u];

    const uint4* np = (const uint4*)g_nodes + sub;   // row = 8 uint4

    // 24 flat gathers
    uint4 a0  = np[(unsigned)s0.x * 8u];
    uint4 b0  = np[(unsigned)d0.x * 8u];
    uint4 a1  = np[(unsigned)s0.y * 8u];
    uint4 b1  = np[(unsigned)d0.y * 8u];
    uint4 a2  = np[(unsigned)s0.z * 8u];
    uint4 b2  = np[(unsigned)d0.z * 8u];
    uint4 a3  = np[(unsigned)s0.w * 8u];
    uint4 b3  = np[(unsigned)d0.w * 8u];
    uint4 a4  = np[(unsigned)s1.x * 8u];
    uint4 b4  = np[(unsigned)d1.x * 8u];
    uint4 a5  = np[(unsigned)s1.y * 8u];
    uint4 b5  = np[(unsigned)d1.y * 8u];
    uint4 a6  = np[(unsigned)s1.z * 8u];
    uint4 b6  = np[(unsigned)d1.z * 8u];
    uint4 a7  = np[(unsigned)s1.w * 8u];
    uint4 b7  = np[(unsigned)d1.w * 8u];
    uint4 a8  = np[(unsigned)s2.x * 8u];
    uint4 b8  = np[(unsigned)d2.x * 8u];
    uint4 a9  = np[(unsigned)s2.y * 8u];
    uint4 b9  = np[(unsigned)d2.y * 8u];
    uint4 a10 = np[(unsigned)s2.z * 8u];
    uint4 b10 = np[(unsigned)d2.z * 8u];
    uint4 a11 = np[(unsigned)s2.w * 8u];
    uint4 b11 = np[(unsigned)d2.w * 8u];

    __half2 p0  = pdot(a0,  b0);
    __half2 p1  = pdot(a1,  b1);
    __half2 p2  = pdot(a2,  b2);
    __half2 p3  = pdot(a3,  b3);
    __half2 p4  = pdot(a4,  b4);
    __half2 p5  = pdot(a5,  b5);
    __half2 p6  = pdot(a6,  b6);
    __half2 p7  = pdot(a7,  b7);
    __half2 p8  = pdot(a8,  b8);
    __half2 p9  = pdot(a9,  b9);
    __half2 p10 = pdot(a10, b10);
    __half2 p11 = pdot(a11, b11);

    bool bit2 = (sub & 4u) != 0u;
    bool bit1 = (sub & 2u) != 0u;
    bool bit0 = (sub & 1u) != 0u;

    // ---- reduce first 8 edges: value-halving, lane sub ends owning edge sub ----
    __half2 w0, w1, w2, w3;
    {
        __half2 q0 = bit2 ? p0 : p4;
        __half2 q1 = bit2 ? p1 : p5;
        __half2 q2 = bit2 ? p2 : p6;
        __half2 q3 = bit2 ? p3 : p7;
        w0 = __hadd2(bit2 ? p4 : p0, shfl_h2(q0, 4));
        w1 = __hadd2(bit2 ? p5 : p1, shfl_h2(q1, 4));
        w2 = __hadd2(bit2 ? p6 : p2, shfl_h2(q2, 4));
        w3 = __hadd2(bit2 ? p7 : p3, shfl_h2(q3, 4));
    }
    __half2 x0, x1;
    {
        __half2 q0 = bit1 ? w0 : w2;
        __half2 q1 = bit1 ? w1 : w3;
        x0 = __hadd2(bit1 ? w2 : w0, shfl_h2(q0, 2));
        x1 = __hadd2(bit1 ? w3 : w1, shfl_h2(q1, 2));
    }
    __half2 qA = bit0 ? x0 : x1;
    __half2 yA = __hadd2(bit0 ? x1 : x0, shfl_h2(qA, 1));

    // ---- reduce last 4 edges (8..11): 4->2->1->dup; even lanes own edge sub>>1 ----
    __half2 u0, u1;
    {
        __half2 q0 = bit2 ? p8 : p10;
        __half2 q1 = bit2 ? p9 : p11;
        u0 = __hadd2(bit2 ? p10 : p8, shfl_h2(q0, 4));
        u1 = __hadd2(bit2 ? p11 : p9, shfl_h2(q1, 4));
    }
    __half2 qB = bit1 ? u0 : u1;
    __half2 xB = __hadd2(bit1 ? u1 : u0, shfl_h2(qB, 2));
    __half2 yB = __hadd2(xB, shfl_h2(xB, 1));

    float2 fA = __half22float2(yA);
    out[g * 12u + sub] = (fA.x + fA.y) * INV_TBL_SCALE2;
    if (!bit0) {
        float2 fB = __half22float2(yB);
        out[g * 12u + 8u + (sub >> 1)] = (fB.x + fB.y) * INV_TBL_SCALE2;
    }
}

// Tail: leftover edges (N_EDGES % 12), one 8-lane group per edge, simple.
__global__ void edge_dot_tail_kernel(const int* __restrict__ src,
                                     const int* __restrict__ dst,
                                     float* __restrict__ out) {
    unsigned int t = blockIdx.x * blockDim.x + threadIdx.x;
    unsigned int e   = t >> 3;
    unsigned int sub = t & 7u;
    if (e >= N_TAIL) return;
    unsigned int edge = N_GROUPS12 * 12u + e;

    int s = src[edge];
    int d = dst[edge];
    const uint4* np = (const uint4*)g_nodes + sub;
    __half2 p = pdot(np[(unsigned)s * 8u], np[(unsigned)d * 8u]);
    p = __hadd2(p, shfl_h2(p, 4));
    p = __hadd2(p, shfl_h2(p, 2));
    p = __hadd2(p, shfl_h2(p, 1));
    if (sub == 0) {
        float2 f = __half22float2(p);
        out[edge] = (f.x + f.y) * INV_TBL_SCALE2;
    }
}

extern "C" void kernel_launch(void* const* d_in, const int* in_sizes, int n_in,
                              void* d_out, int out_size) {
    const float* user_emb     = (const float*)d_in[0];
    const float* item_emb     = (const float*)d_in[1];
    const float* tag_emb      = (const float*)d_in[2];
    const float* testid_emb   = (const float*)d_in[3];
    const float* bigcat_emb   = (const float*)d_in[4];
    const float* daydiff_emb  = (const float*)d_in[5];
    const int*   edge_index   = (const int*)d_in[6];   // [2, N_EDGES] int32
    const int*   item_tags    = (const int*)d_in[7];
    const int*   item_testids = (const int*)d_in[8];
    const int*   item_bigcat  = (const int*)d_in[9];
    const int*   user_daydiff = (const int*)d_in[10];

    // Phase 1: 60000 nodes * 16 threads
    {
        unsigned int total = NUM_NODES * 16u;
        unsigned int threads = 256;
        unsigned int blocks = (total + threads - 1) / threads;
        build_nodes_kernel<<<blocks, threads>>>(user_emb, item_emb, tag_emb,
                                                testid_emb, bigcat_emb, daydiff_emb,
                                                item_tags, item_testids, item_bigcat,
                                                user_daydiff);
    }

    // Phase 2 main: 166666 groups * 8 threads
    {
        const int4* src4 = (const int4*)edge_index;
        const int4* dst4 = (const int4*)(edge_index + N_EDGES);
        unsigned int total = N_GROUPS12 * 8u;
        unsigned int threads = 256;
        unsigned int blocks = (total + threads - 1) / threads;
        edge_dot_kernel<<<blocks, threads>>>(src4, dst4, (float*)d_out);
    }

    // Phase 2 tail: N_EDGES % 12 edges
    if (N_TAIL > 0) {
        unsigned int total = N_TAIL * 8u;
        unsigned int threads = 256;
        unsigned int blocks = (total + threads - 1) / threads;
        edge_dot_tail_kernel<<<blocks, threads>>>(edge_index,
                                                  edge_index + N_EDGES,
                                                  (float*)d_out);
    }
}

// round 13
// speedup vs baseline: 1.0063x; 1.0063x over previous
#include <cuda_runtime.h>
#include <cuda_fp16.h>

#define N_USER    50000
#define N_ITEM    10000
#define NUM_NODES 60000
#define EMB_D     64
#define N_EDGES   2000000
#define N_GROUPS8 (N_EDGES / 8)   // 8 edges per 8-lane group

// Table scale: keeps fp16 products in normal range.
#define TBL_SCALE      512.0f
#define INV_TBL_SCALE2 (1.0f / (512.0f * 512.0f))   // 2^-18

// Fused, pre-scaled node table in fp16: row = 64 half = 128 B (one L1 line).
__device__ __half g_nodes[NUM_NODES * EMB_D];

// Phase 1: build fused node table (fp32 math, fp16 store, x512 pre-scale).
__global__ void build_nodes_kernel(const float* __restrict__ user_emb,
                                   const float* __restrict__ item_emb,
                                   const float* __restrict__ tag_emb,
                                   const float* __restrict__ testid_emb,
                                   const float* __restrict__ bigcat_emb,
                                   const float* __restrict__ daydiff_emb,
                                   const int*  __restrict__ item_tags,
                                   const int*  __restrict__ item_testids,
                                   const int*  __restrict__ item_bigcat,
                                   const int*  __restrict__ user_daydiff) {
    unsigned int t = blockIdx.x * blockDim.x + threadIdx.x;
    unsigned int node = t >> 4;
    unsigned int sub  = t & 15u;
    if (node >= NUM_NODES) return;
    unsigned int off = sub * 4u;

    const float alpha = 1.0f / 3.0f;
    float4 r;
    if (node < N_USER) {
        const float s = 0.5f * alpha * TBL_SCALE;
        int dd = user_daydiff[node];
        float4 u = *(const float4*)(user_emb    + (size_t)node * EMB_D + off);
        float4 d = *(const float4*)(daydiff_emb + (size_t)dd   * EMB_D + off);
        r.x = (u.x + d.x) * s;
        r.y = (u.y + d.y) * s;
        r.z = (u.z + d.z) * s;
        r.w = (u.w + d.w) * s;
    } else {
        const float s = 0.25f * alpha * TBL_SCALE;
        unsigned int it = node - N_USER;
        int tg = item_tags[it];
        int ts = item_testids[it];
        int bc = item_bigcat[it];
        float4 a = *(const float4*)(item_emb   + (size_t)it * EMB_D + off);
        float4 b = *(const float4*)(tag_emb    + (size_t)tg * EMB_D + off);
        float4 c = *(const float4*)(testid_emb + (size_t)ts * EMB_D + off);
        float4 e = *(const float4*)(bigcat_emb + (size_t)bc * EMB_D + off);
        r.x = (a.x + b.x + c.x + e.x) * s;
        r.y = (a.y + b.y + c.y + e.y) * s;
        r.z = (a.z + b.z + c.z + e.z) * s;
        r.w = (a.w + b.w + c.w + e.w) * s;
    }
    __half2 h0 = __floats2half2_rn(r.x, r.y);
    __half2 h1 = __floats2half2_rn(r.z, r.w);
    uint2 packed;
    packed.x = *(const unsigned int*)&h0;
    packed.y = *(const unsigned int*)&h1;
    *(uint2*)((char*)g_nodes + (size_t)node * 128u + sub * 8u) = packed;
}

// half2 partial dot of 16 halves (one uint4 pair): 4 HMUL2 + 3 HADD2.
__device__ __forceinline__ __half2 pdot(uint4 a, uint4 b) {
    const __half2* pa = (const __half2*)&a;
    const __half2* pb = (const __half2*)&b;
    __half2 m0 = __hmul2(pa[0], pb[0]);
    __half2 m1 = __hmul2(pa[1], pb[1]);
    __half2 m2 = __hmul2(pa[2], pb[2]);
    __half2 m3 = __hmul2(pa[3], pb[3]);
    return __hadd2(__hadd2(m0, m1), __hadd2(m2, m3));
}

__device__ __forceinline__ __half2 shfl_h2(__half2 v, int ofs) {
    unsigned int u = *(unsigned int*)&v;
    u = __shfl_xor_sync(0xffffffffu, u, ofs);
    return *(__half2*)&u;
}

// Phase 2: grid-stride loop; each iteration is R5's proven-best body
// (8 edges per 8-lane group, 16 flat LDG.128 gathers, 7-SHFL reduction).
// Persistent-ish blocks keep warps resident -> achieved occupancy ~100%
// instead of R5's 65% (short-block drain/launch gaps).
__global__ __launch_bounds__(256) void edge_dot_kernel(
        const int4* __restrict__ src4,
        const int4* __restrict__ dst4,
        float* __restrict__ out) {
    unsigned int tid0  = blockIdx.x * blockDim.x + threadIdx.x;
    unsigned int sub   = tid0 & 7u;
    unsigned int g0    = tid0 >> 3;
    unsigned int gstep = (gridDim.x * blockDim.x) >> 3;

    const uint4* np = (const uint4*)g_nodes + sub;   // row = 8 uint4

    bool bit2 = (sub & 4u) != 0u;
    bool bit1 = (sub & 2u) != 0u;
    bool bit0 = (sub & 1u) != 0u;

    for (unsigned int g = g0; g < N_GROUPS8; g += gstep) {
        int4 sL = src4[g * 2u];
        int4 sH = src4[g * 2u + 1u];
        int4 dL = dst4[g * 2u];
        int4 dH = dst4[g * 2u + 1u];

        uint4 a0 = np[(unsigned)sL.x * 8u];
        uint4 b0 = np[(unsigned)dL.x * 8u];
        uint4 a1 = np[(unsigned)sL.y * 8u];
        uint4 b1 = np[(unsigned)dL.y * 8u];
        uint4 a2 = np[(unsigned)sL.z * 8u];
        uint4 b2 = np[(unsigned)dL.z * 8u];
        uint4 a3 = np[(unsigned)sL.w * 8u];
        uint4 b3 = np[(unsigned)dL.w * 8u];
        uint4 a4 = np[(unsigned)sH.x * 8u];
        uint4 b4 = np[(unsigned)dH.x * 8u];
        uint4 a5 = np[(unsigned)sH.y * 8u];
        uint4 b5 = np[(unsigned)dH.y * 8u];
        uint4 a6 = np[(unsigned)sH.z * 8u];
        uint4 b6 = np[(unsigned)dH.z * 8u];
        uint4 a7 = np[(unsigned)sH.w * 8u];
        uint4 b7 = np[(unsigned)dH.w * 8u];

        __half2 p0 = pdot(a0, b0);
        __half2 p1 = pdot(a1, b1);
        __half2 p2 = pdot(a2, b2);
        __half2 p3 = pdot(a3, b3);
        __half2 p4 = pdot(a4, b4);
        __half2 p5 = pdot(a5, b5);
        __half2 p6 = pdot(a6, b6);
        __half2 p7 = pdot(a7, b7);

        // Stage 1 (xor 4): 8 -> 4 values.
        __half2 w0, w1, w2, w3;
        {
            __half2 q0 = bit2 ? p0 : p4;
            __half2 q1 = bit2 ? p1 : p5;
            __half2 q2 = bit2 ? p2 : p6;
            __half2 q3 = bit2 ? p3 : p7;
            w0 = __hadd2(bit2 ? p4 : p0, shfl_h2(q0, 4));
            w1 = __hadd2(bit2 ? p5 : p1, shfl_h2(q1, 4));
            w2 = __hadd2(bit2 ? p6 : p2, shfl_h2(q2, 4));
            w3 = __hadd2(bit2 ? p7 : p3, shfl_h2(q3, 4));
        }
        // Stage 2 (xor 2): 4 -> 2.
        __half2 x0, x1;
        {
            __half2 q0 = bit1 ? w0 : w2;
            __half2 q1 = bit1 ? w1 : w3;
            x0 = __hadd2(bit1 ? w2 : w0, shfl_h2(q0, 2));
            x1 = __hadd2(bit1 ? w3 : w1, shfl_h2(q1, 2));
        }
        // Stage 3 (xor 1): 2 -> 1. Lane `sub` owns edge g*8+sub.
        __half2 q = bit0 ? x0 : x1;
        __half2 y = __hadd2(bit0 ? x1 : x0, shfl_h2(q, 1));

        float2 f = __half22float2(y);
        out[g * 8u + sub] = (f.x + f.y) * INV_TBL_SCALE2;
    }
}

extern "C" void kernel_launch(void* const* d_in, const int* in_sizes, int n_in,
                              void* d_out, int out_size) {
    const float* user_emb     = (const float*)d_in[0];
    const float* item_emb     = (const float*)d_in[1];
    const float* tag_emb      = (const float*)d_in[2];
    const float* testid_emb   = (const float*)d_in[3];
    const float* bigcat_emb   = (const float*)d_in[4];
    const float* daydiff_emb  = (const float*)d_in[5];
    const int*   edge_index   = (const int*)d_in[6];   // [2, N_EDGES] int32
    const int*   item_tags    = (const int*)d_in[7];
    const int*   item_testids = (const int*)d_in[8];
    const int*   item_bigcat  = (const int*)d_in[9];
    const int*   user_daydiff = (const int*)d_in[10];

    // Phase 1: 60000 nodes * 16 threads
    {
        unsigned int total = NUM_NODES * 16u;
        unsigned int threads = 256;
        unsigned int blocks = (total + threads - 1) / threads;
        build_nodes_kernel<<<blocks, threads>>>(user_emb, item_emb, tag_emb,
                                                testid_emb, bigcat_emb, daydiff_emb,
                                                item_tags, item_testids, item_bigcat,
                                                user_daydiff);
    }

    // Phase 2: persistent-ish grid — ~4 blocks/SM, grid-stride over 250K groups.
    {
        const int4* src4 = (const int4*)edge_index;
        const int4* dst4 = (const int4*)(edge_index + N_EDGES);
        unsigned int blocks = 148 * 4;
        edge_dot_kernel<<<blocks, 256>>>(src4, dst4, (float*)d_out);
    }
}

// round 15
// speedup vs baseline: 1.0393x; 1.0327x over previous
#include <cuda_runtime.h>
#include <cuda_fp16.h>

#define N_USER    50000
#define N_ITEM    10000
#define NUM_NODES 60000
#define EMB_D     64
#define N_EDGES   2000000
#define N_GROUPS8 (N_EDGES / 8)   // 8 edges per 8-lane group

// Table scale: keeps fp16 products in normal range.
#define TBL_SCALE      512.0f
#define INV_TBL_SCALE2 (1.0f / (512.0f * 512.0f))   // 2^-18

// Fused, pre-scaled node table in fp16: row = 64 half = 128 B (one L1 line).
__device__ __half g_nodes[NUM_NODES * EMB_D];

// Compute one node's fused float4 slice (dims [off, off+4)).
__device__ __forceinline__ float4 fuse_node(
        unsigned int node, unsigned int off,
        const float* __restrict__ user_emb,
        const float* __restrict__ item_emb,
        const float* __restrict__ tag_emb,
        const float* __restrict__ testid_emb,
        const float* __restrict__ bigcat_emb,
        const float* __restrict__ daydiff_emb,
        const int*  __restrict__ item_tags,
        const int*  __restrict__ item_testids,
        const int*  __restrict__ item_bigcat,
        const int*  __restrict__ user_daydiff) {
    const float alpha = 1.0f / 3.0f;
    float4 r;
    if (node < N_USER) {
        const float s = 0.5f * alpha * TBL_SCALE;
        int dd = user_daydiff[node];
        float4 u = *(const float4*)(user_emb    + (size_t)node * EMB_D + off);
        float4 d = *(const float4*)(daydiff_emb + (size_t)dd   * EMB_D + off);
        r.x = (u.x + d.x) * s;
        r.y = (u.y + d.y) * s;
        r.z = (u.z + d.z) * s;
        r.w = (u.w + d.w) * s;
    } else {
        const float s = 0.25f * alpha * TBL_SCALE;
        unsigned int it = node - N_USER;
        int tg = item_tags[it];
        int ts = item_testids[it];
        int bc = item_bigcat[it];
        float4 a = *(const float4*)(item_emb   + (size_t)it * EMB_D + off);
        float4 b = *(const float4*)(tag_emb    + (size_t)tg * EMB_D + off);
        float4 c = *(const float4*)(testid_emb + (size_t)ts * EMB_D + off);
        float4 e = *(const float4*)(bigcat_emb + (size_t)bc * EMB_D + off);
        r.x = (a.x + b.x + c.x + e.x) * s;
        r.y = (a.y + b.y + c.y + e.y) * s;
        r.z = (a.z + b.z + c.z + e.z) * s;
        r.w = (a.w + b.w + c.w + e.w) * s;
    }
    return r;
}

__device__ __forceinline__ void store_h4(unsigned int node, unsigned int sub, float4 r) {
    __half2 h0 = __floats2half2_rn(r.x, r.y);
    __half2 h1 = __floats2half2_rn(r.z, r.w);
    uint2 packed;
    packed.x = *(const unsigned int*)&h0;
    packed.y = *(const unsigned int*)&h1;
    *(uint2*)((char*)g_nodes + (size_t)node * 128u + sub * 8u) = packed;
}

// Phase 1: each thread fuses TWO nodes (node and node + NUM_NODES/2) —
// doubles independent gathers in flight per thread (build is latency-bound).
__global__ __launch_bounds__(256) void build_nodes_kernel(
        const float* __restrict__ user_emb,
        const float* __restrict__ item_emb,
        const float* __restrict__ tag_emb,
        const float* __restrict__ testid_emb,
        const float* __restrict__ bigcat_emb,
        const float* __restrict__ daydiff_emb,
        const int*  __restrict__ item_tags,
        const int*  __restrict__ item_testids,
        const int*  __restrict__ item_bigcat,
        const int*  __restrict__ user_daydiff) {
    unsigned int t = blockIdx.x * blockDim.x + threadIdx.x;
    unsigned int node = t >> 4;                 // 0 .. NUM_NODES/2-1
    unsigned int sub  = t & 15u;
    if (node >= NUM_NODES / 2) return;
    unsigned int off = sub * 4u;
    unsigned int node2 = node + NUM_NODES / 2;  // second half

    float4 r0 = fuse_node(node,  off, user_emb, item_emb, tag_emb, testid_emb,
                          bigcat_emb, daydiff_emb, item_tags, item_testids,
                          item_bigcat, user_daydiff);
    float4 r1 = fuse_node(node2, off, user_emb, item_emb, tag_emb, testid_emb,
                          bigcat_emb, daydiff_emb, item_tags, item_testids,
                          item_bigcat, user_daydiff);
    store_h4(node,  sub, r0);
    store_h4(node2, sub, r1);
}

// half2 partial dot of 16 halves (one uint4 pair): 4 HMUL2 + 3 HADD2.
__device__ __forceinline__ __half2 pdot(uint4 a, uint4 b) {
    const __half2* pa = (const __half2*)&a;
    const __half2* pb = (const __half2*)&b;
    __half2 m0 = __hmul2(pa[0], pb[0]);
    __half2 m1 = __hmul2(pa[1], pb[1]);
    __half2 m2 = __hmul2(pa[2], pb[2]);
    __half2 m3 = __hmul2(pa[3], pb[3]);
    return __hadd2(__hadd2(m0, m1), __hadd2(m2, m3));
}

__device__ __forceinline__ __half2 shfl_h2(__half2 v, int ofs) {
    unsigned int u = *(unsigned int*)&v;
    u = __shfl_xor_sync(0xffffffffu, u, ofs);
    return *(__half2*)&u;
}

// Phase 2: 8 edges per 8-lane group — byte-exact R5 structure (proven best:
// 16 flat LDG.128 gathers, ~40 regs, 6 blocks/SM). 7-SHFL value-halving
// reduction; lane `sub` ends owning edge g*8+sub -> warp-coalesced store.
__global__ __launch_bounds__(256) void edge_dot_kernel(
        const int4* __restrict__ src4,
        const int4* __restrict__ dst4,
        float* __restrict__ out) {
    unsigned int t = blockIdx.x * blockDim.x + threadIdx.x;
    unsigned int g   = t >> 3;
    unsigned int sub = t & 7u;
    if (g >= N_GROUPS8) return;

    int4 sL = src4[g * 2u];
    int4 sH = src4[g * 2u + 1u];
    int4 dL = dst4[g * 2u];
    int4 dH = dst4[g * 2u + 1u];

    const uint4* np = (const uint4*)g_nodes + sub;   // row = 8 uint4

    uint4 a0 = np[(unsigned)sL.x * 8u];
    uint4 b0 = np[(unsigned)dL.x * 8u];
    uint4 a1 = np[(unsigned)sL.y * 8u];
    uint4 b1 = np[(unsigned)dL.y * 8u];
    uint4 a2 = np[(unsigned)sL.z * 8u];
    uint4 b2 = np[(unsigned)dL.z * 8u];
    uint4 a3 = np[(unsigned)sL.w * 8u];
    uint4 b3 = np[(unsigned)dL.w * 8u];
    uint4 a4 = np[(unsigned)sH.x * 8u];
    uint4 b4 = np[(unsigned)dH.x * 8u];
    uint4 a5 = np[(unsigned)sH.y * 8u];
    uint4 b5 = np[(unsigned)dH.y * 8u];
    uint4 a6 = np[(unsigned)sH.z * 8u];
    uint4 b6 = np[(unsigned)dH.z * 8u];
    uint4 a7 = np[(unsigned)sH.w * 8u];
    uint4 b7 = np[(unsigned)dH.w * 8u];

    __half2 p0 = pdot(a0, b0);
    __half2 p1 = pdot(a1, b1);
    __half2 p2 = pdot(a2, b2);
    __half2 p3 = pdot(a3, b3);
    __half2 p4 = pdot(a4, b4);
    __half2 p5 = pdot(a5, b5);
    __half2 p6 = pdot(a6, b6);
    __half2 p7 = pdot(a7, b7);

    bool bit2 = (sub & 4u) != 0u;
    bool bit1 = (sub & 2u) != 0u;
    bool bit0 = (sub & 1u) != 0u;

    // Stage 1 (xor 4): 8 -> 4 values.
    __half2 w0, w1, w2, w3;
    {
        __half2 q0 = bit2 ? p0 : p4;
        __half2 q1 = bit2 ? p1 : p5;
        __half2 q2 = bit2 ? p2 : p6;
        __half2 q3 = bit2 ? p3 : p7;
        w0 = __hadd2(bit2 ? p4 : p0, shfl_h2(q0, 4));
        w1 = __hadd2(bit2 ? p5 : p1, shfl_h2(q1, 4));
        w2 = __hadd2(bit2 ? p6 : p2, shfl_h2(q2, 4));
        w3 = __hadd2(bit2 ? p7 : p3, shfl_h2(q3, 4));
    }
    // Stage 2 (xor 2): 4 -> 2.
    __half2 x0, x1;
    {
        __half2 q0 = bit1 ? w0 : w2;
        __half2 q1 = bit1 ? w1 : w3;
        x0 = __hadd2(bit1 ? w2 : w0, shfl_h2(q0, 2));
        x1 = __hadd2(bit1 ? w3 : w1, shfl_h2(q1, 2));
    }
    // Stage 3 (xor 1): 2 -> 1. Lane `sub` owns edge g*8+sub.
    __half2 q = bit0 ? x0 : x1;
    __half2 y = __hadd2(bit0 ? x1 : x0, shfl_h2(q, 1));

    float2 f = __half22float2(y);
    out[g * 8u + sub] = (f.x + f.y) * INV_TBL_SCALE2;
}

extern "C" void kernel_launch(void* const* d_in, const int* in_sizes, int n_in,
                              void* d_out, int out_size) {
    const float* user_emb     = (const float*)d_in[0];
    const float* item_emb     = (const float*)d_in[1];
    const float* tag_emb      = (const float*)d_in[2];
    const float* testid_emb   = (const float*)d_in[3];
    const float* bigcat_emb   = (const float*)d_in[4];
    const float* daydiff_emb  = (const float*)d_in[5];
    const int*   edge_index   = (const int*)d_in[6];   // [2, N_EDGES] int32
    const int*   item_tags    = (const int*)d_in[7];
    const int*   item_testids = (const int*)d_in[8];
    const int*   item_bigcat  = (const int*)d_in[9];
    const int*   user_daydiff = (const int*)d_in[10];

    // Phase 1: 30000 node-pairs * 16 threads
    {
        unsigned int total = (NUM_NODES / 2) * 16u;
        unsigned int threads = 256;
        unsigned int blocks = (total + threads - 1) / threads;
        build_nodes_kernel<<<blocks, threads>>>(user_emb, item_emb, tag_emb,
                                                testid_emb, bigcat_emb, daydiff_emb,
                                                item_tags, item_testids, item_bigcat,
                                                user_daydiff);
    }

    // Phase 2: 250K groups * 8 threads = 2M threads (R5 launch shape)
    {
        const int4* src4 = (const int4*)edge_index;
        const int4* dst4 = (const int4*)(edge_index + N_EDGES);
        unsigned int total = N_GROUPS8 * 8u;
        unsigned int threads = 256;
        unsigned int blocks = (total + threads - 1) / threads;
        edge_dot_kernel<<<blocks, threads>>>(src4, dst4, (float*)d_out);
    }
}